// round 12
// baseline (speedup 1.0000x reference)
#include <cuda_runtime.h>
#include <cuda_bf16.h>
#include <cstdint>

// Problem constants
#define Bn 64
#define Sn 128
#define Tn 64
#define Fp 100
#define M_TOTAL (Bn*Sn*Tn)   // 524288

#define NSCAN   64           // scan CTAs (one per batch)
#define NWORK   84           // GEMM worker CTAs
#define NBLK    2048         // 256-row GEMM blocks total (64 b x 32 groups)

__device__ float g_xw[(size_t)M_TOTAL * Fp];
__device__ int   g_flag[NBLK];

namespace {
struct ForceLoad {
    ForceLoad() {
        void* p = nullptr;
        cudaGetSymbolAddress(&p, g_xw);
        cudaGetSymbolAddress(&p, g_flag);
    }
};
ForceLoad g_force_load_;
}

// ---------------------------------------------------------------------------
// Shared constants / helpers
// ---------------------------------------------------------------------------
#define GMT 256
#define SX_LD 258
#define SW_LD 104

#define NT 512
#define NM 384
#define TILE_LD 104
#define TILE_CHUNKS (Tn*(Fp/4))    // 1600 x 16B

// scan SMEM float offsets (GEMM workers reuse the front of the same buffer)
#define OFF_WH    0       // 30000
#define OFF_WC    30000   // 10000
#define OFF_XW    40000   // 6656
#define OFF_X     46656   // 6656
#define OFF_U     53312   // 100
#define OFF_BG    53412   // 300
#define OFF_H     53712   // 100
#define OFF_C     53812   // 100
#define OFF_A     53912   // 64
#define OFF_PART  53976   // 200
#define OFF_GX    54176   // 300
#define OFF_GH    54476   // 300
#define OFF_ATT   54776   // 100
#define OFF_INV   54876   // 4
#define SCAN_SMEM_FLOATS 54880
#define SCAN_SMEM_BYTES (SCAN_SMEM_FLOATS*4)   // 219520

__device__ __forceinline__ unsigned long long pack2(float a, float b) {
    unsigned long long r;
    asm("mov.b64 %0, {%1, %2};" : "=l"(r) : "f"(a), "f"(b));
    return r;
}
__device__ __forceinline__ float2 unpack2(unsigned long long v) {
    float2 r;
    asm("mov.b64 {%0, %1}, %2;" : "=f"(r.x), "=f"(r.y) : "l"(v));
    return r;
}
__device__ __forceinline__ float tanh_fast(float x) {
    float y;
    asm("tanh.approx.f32 %0, %1;" : "=f"(y) : "f"(x));
    return y;
}
__device__ __forceinline__ float fast_sigmoid(float v) {
    return 1.f / (1.f + __expf(-v));
}
__device__ __forceinline__ void cp_async16(uint32_t smem_addr, const void* gptr) {
    asm volatile("cp.async.cg.shared.global [%0], [%1], 16;"
                 :: "r"(smem_addr), "l"(gptr));
}
__device__ __forceinline__ void cp_commit() {
    asm volatile("cp.async.commit_group;");
}
__device__ __forceinline__ void cp_wait0() {
    asm volatile("cp.async.wait_group 0;");
}
__device__ __forceinline__ void barM() {
    asm volatile("bar.sync 1, %0;" :: "n"(NM) : "memory");
}
__device__ __forceinline__ void set_flag_release(int* p) {
    asm volatile("st.release.gpu.global.b32 [%0], %1;" :: "l"(p), "r"(1) : "memory");
}
__device__ __forceinline__ void wait_flag_acquire(const int* p) {
    int v;
    while (true) {
        asm volatile("ld.acquire.gpu.global.b32 %0, [%1];" : "=r"(v) : "l"(p) : "memory");
        if (v) break;
        __nanosleep(64);
    }
}

// ---------------------------------------------------------------------------
// flag reset (must precede fused kernel every call; deterministic per replay)
// ---------------------------------------------------------------------------
__global__ void zero_flags_kernel() {
    int i = blockIdx.x * blockDim.x + threadIdx.x;
    if (i < NBLK) g_flag[i] = 0;
}

// ---------------------------------------------------------------------------
// GEMM worker body: persistent loop over blocks j = w, w+NWORK, ...
// j -> (b = j & 63, g = j >> 6); block rows m0 = b*8192 + g*256.
// g-major global order => for step s, scan CTA b needs flag[(s>>2)*64 + b].
// Threads 0..415 compute (32 m-lanes x 13 n-groups, 8x8 f32x2 tile);
// threads 416..511 only help with loads / barriers.
// ---------------------------------------------------------------------------
__device__ void gemm_body(const float* __restrict__ x,
                          const float* __restrict__ W,
                          const float* __restrict__ bias,
                          float* sm)
{
    float* sX = sm;                  // [100][SX_LD]
    float* sW = sm + Fp*SX_LD;       // [100][SW_LD]

    const int tid = threadIdx.x;
    const int w   = blockIdx.x - NSCAN;

    // W (+pad) loaded once, reused across all blocks of this worker
    for (int i = tid; i < Fp*SW_LD; i += NT) {
        int k = i / SW_LD, n = i - k*SW_LD;
        sW[i] = (n < Fp) ? W[k*Fp + n] : 0.f;
    }

    const bool active = (tid < 416);
    const int mi = tid & 31;
    const int ni = tid >> 5;
    const int nbase = ni * 8;
    const uint32_t sa = (uint32_t)__cvta_generic_to_shared(sX) + (uint32_t)mi*8u;
    const float* wrow = sW + nbase;

    float bb[8];
    if (active) {
        #pragma unroll
        for (int n = 0; n < 8; n++) {
            int nb = nbase + n;
            bb[n] = (nb < Fp) ? bias[nb] : 0.f;
        }
    }

    for (int j = w; j < NBLK; j += NWORK) {
        const int b = j & 63;
        const int g = j >> 6;
        const size_t m0 = (size_t)b * (Sn*(size_t)Tn) + (size_t)g * GMT;

        __syncthreads();   // prior block's sX reads done (also publishes sW 1st iter)
        for (int i = tid; i < GMT*Fp; i += NT) {
            int m = i / Fp, k = i - m*Fp;
            sX[k*SX_LD + m] = x[(m0 + m)*Fp + k];
        }
        __syncthreads();

        if (active) {
            unsigned long long acc[4][8];
            #pragma unroll
            for (int p = 0; p < 4; p++)
                #pragma unroll
                for (int n = 0; n < 8; n++) acc[p][n] = 0ull;

            #pragma unroll 2
            for (int k = 0; k < Fp; k++) {
                unsigned long long ap[4];
                #pragma unroll
                for (int p = 0; p < 4; p++)
                    asm("ld.shared.b64 %0, [%1];"
                        : "=l"(ap[p])
                        : "r"(sa + (uint32_t)((k*SX_LD + 64*p)*4)));
                float4 b0 = *(const float4*)(wrow + k*SW_LD);
                float4 b1 = *(const float4*)(wrow + k*SW_LD + 4);
                unsigned long long bd[8];
                bd[0] = pack2(b0.x, b0.x); bd[1] = pack2(b0.y, b0.y);
                bd[2] = pack2(b0.z, b0.z); bd[3] = pack2(b0.w, b0.w);
                bd[4] = pack2(b1.x, b1.x); bd[5] = pack2(b1.y, b1.y);
                bd[6] = pack2(b1.z, b1.z); bd[7] = pack2(b1.w, b1.w);
                #pragma unroll
                for (int p = 0; p < 4; p++)
                    #pragma unroll
                    for (int n = 0; n < 8; n++)
                        asm("fma.rn.f32x2 %0, %1, %2, %0;"
                            : "+l"(acc[p][n]) : "l"(ap[p]), "l"(bd[n]));
            }

            #pragma unroll
            for (int p = 0; p < 4; p++) {
                float2 v[8];
                #pragma unroll
                for (int n = 0; n < 8; n++) v[n] = unpack2(acc[p][n]);
                const size_t r0 = m0 + 2*mi + 64*p;
                float* o0 = g_xw + r0*Fp + nbase;
                float* o1 = o0 + Fp;
                float4 lo0 = { v[0].x+bb[0], v[1].x+bb[1], v[2].x+bb[2], v[3].x+bb[3] };
                float4 lo1 = { v[0].y+bb[0], v[1].y+bb[1], v[2].y+bb[2], v[3].y+bb[3] };
                *(float4*)o0 = lo0;
                *(float4*)o1 = lo1;
                if (ni < 12) {
                    float4 hi0 = { v[4].x+bb[4], v[5].x+bb[5], v[6].x+bb[6], v[7].x+bb[7] };
                    float4 hi1 = { v[4].y+bb[4], v[5].y+bb[5], v[6].y+bb[6], v[7].y+bb[7] };
                    *(float4*)(o0 + 4) = hi0;
                    *(float4*)(o1 + 4) = hi1;
                }
            }
        }

        __threadfence();     // each thread's g_xw stores visible at gpu scope
        __syncthreads();     // ...for ALL threads, before the flag
        if (tid == 0) set_flag_release(&g_flag[j]);
    }
}

// ---------------------------------------------------------------------------
// scan tile staging
// ---------------------------------------------------------------------------
__device__ __forceinline__ void stage_tile(uint32_t smem_base_bytes,
                                           const float* gsrc, int tid) {
    #pragma unroll 2
    for (int i = tid; i < TILE_CHUNKS; i += NM) {
        int t = i / (Fp/4);
        int c = i - t*(Fp/4);
        cp_async16(smem_base_bytes + (uint32_t)(t*TILE_LD + c*4)*4u,
                   gsrc + (size_t)i*4);
    }
}

// ---------------------------------------------------------------------------
// Scan body: identical to R8 warp-specialized scan + producer flag waits.
// ---------------------------------------------------------------------------
__device__ void scan_body(const float* __restrict__ x,
                          const float* __restrict__ Wc,
                          const float* __restrict__ u,
                          const float* __restrict__ Wx,
                          const float* __restrict__ Wh,
                          const float* __restrict__ bg,
                          float* __restrict__ out,
                          float* sm)
{
    float* sWh  = sm + OFF_WH;
    float* sWc  = sm + OFF_WC;
    float* sXW  = sm + OFF_XW;
    float* sX   = sm + OFF_X;
    float* su   = sm + OFF_U;
    float* sbg  = sm + OFF_BG;
    float* sh   = sm + OFF_H;
    float* sc   = sm + OFF_C;
    float* sa   = sm + OFF_A;
    float* spart= sm + OFF_PART;
    float* sgx  = sm + OFF_GX;
    float* sgh  = sm + OFF_GH;
    float* satt = sm + OFF_ATT;
    float* sinv = sm + OFF_INV;

    const int tid  = threadIdx.x;
    const int lane = tid & 31;
    const int wid  = tid >> 5;   // 0..15
    const int b    = blockIdx.x;
    const bool isM = (tid < NM);

    const uint32_t sm_bytes = (uint32_t)__cvta_generic_to_shared(sm);

    // weights first (overlaps the GEMM producing group 0)
    {
        const float4* wh4 = (const float4*)Wh;
        float4* swh4 = (float4*)sWh;
        for (int i = tid; i < (Fp*3*Fp)/4; i += NT) swh4[i] = wh4[i];
        const float4* wc4 = (const float4*)Wc;
        float4* swc4 = (float4*)sWc;
        for (int i = tid; i < (Fp*Fp)/4; i += NT) swc4[i] = wc4[i];
    }
    if (tid < Fp)   { su[tid] = u[tid]; sh[tid] = 0.f; }
    if (tid < 3*Fp) sbg[tid] = bg[tid];

    if (isM) {
        if (tid == 0) wait_flag_acquire(&g_flag[b]);   // block (b, g=0)
        barM();
        const size_t tile0 = (size_t)(b*Sn) * (Tn*Fp);
        stage_tile(sm_bytes + OFF_XW*4u, g_xw + tile0, tid);
        stage_tile(sm_bytes + OFF_X*4u,  x    + tile0, tid);
        cp_commit();
    }
    __syncthreads();

    const float u0 = su[lane];
    const float u1 = su[lane + 32];
    const float u2 = su[lane + 64];
    const float u3 = (lane < 4) ? su[lane + 96] : 0.f;

    for (int s = 0; s < Sn; s++) {
        if (!isM) {
            // ===== group G: gh = h @ Wh =====
            const int tg = tid - NM;   // 0..127
            float g0 = 0.f, g1 = 0.f, g2 = 0.f;
            #pragma unroll 4
            for (int i = 0; i < Fp; i++) {
                const float hv = sh[i];
                const float* wr = sWh + i*300 + tg;
                g0 = fmaf(hv, wr[0],   g0);
                g1 = fmaf(hv, wr[128], g1);
                g2 = fmaf(hv, wr[256], g2);
            }
            sgh[tg]       = g0;
            sgh[tg + 128] = g1;
            if (tg < 44) sgh[tg + 256] = g2;
        } else {
            // ===== group M =====
            float wx0[25];
            if (tid < 300) {
                #pragma unroll
                for (int q = 0; q < 25; q++)
                    wx0[q] = Wx[q*300 + tid];
            }

            // phase 1: c = h @ W_context
            if (tid < Fp) {
                float a0=0.f, a1=0.f, a2=0.f, a3=0.f;
                #pragma unroll 5
                for (int i = 0; i < Fp; i += 4) {
                    a0 += sh[i+0] * sWc[(i+0)*Fp + tid];
                    a1 += sh[i+1] * sWc[(i+1)*Fp + tid];
                    a2 += sh[i+2] * sWc[(i+2)*Fp + tid];
                    a3 += sh[i+3] * sWc[(i+3)*Fp + tid];
                }
                sc[tid] = (a0 + a1) + (a2 + a3);
            }
            cp_wait0();
            barM();

            // phase 2: a[t] = exp( tanh(xw[t,:] + c) . u )
            {
                const float c0 = sc[lane];
                const float c1 = sc[lane + 32];
                const float c2 = sc[lane + 64];
                const float c3 = (lane < 4) ? sc[lane + 96] : 0.f;
                #pragma unroll
                for (int t = wid; t < Tn; t += 12) {
                    const float* row = sXW + t*TILE_LD;
                    float v0 = row[lane]      + c0;
                    float v1 = row[lane + 32] + c1;
                    float v2 = row[lane + 64] + c2;
                    float v3 = (lane < 4) ? (row[lane + 96] + c3) : 0.f;
                    float p = tanh_fast(v0)*u0 + tanh_fast(v1)*u1
                            + tanh_fast(v2)*u2 + tanh_fast(v3)*u3;
                    #pragma unroll
                    for (int off = 16; off > 0; off >>= 1)
                        p += __shfl_xor_sync(0xffffffffu, p, off);
                    if (lane == 0) sa[t] = __expf(p);
                }
            }
            barM();

            // phase 2b (warp 11) + phase 3 partials (tid<200)
            if (wid == 11) {
                float v = sa[lane] + sa[lane + 32];
                #pragma unroll
                for (int off = 16; off > 0; off >>= 1)
                    v += __shfl_xor_sync(0xffffffffu, v, off);
                if (lane == 0) sinv[0] = 1.f / (v + 1e-7f);
            }
            if (tid < 200) {
                const int f    = (tid < 100) ? tid : tid - 100;
                const int half = (tid < 100) ? 0 : 1;
                const float* xr = sX + (half*32)*TILE_LD + f;
                const float* ar = sa + half*32;
                float acc = 0.f;
                #pragma unroll 8
                for (int t = 0; t < 32; t++)
                    acc += xr[t*TILE_LD] * ar[t];
                spart[tid] = acc;
            }
            barM();

            // phase 3b: attended; prefetch next step's tiles (flag-gated)
            if (tid < Fp) satt[tid] = (spart[tid] + spart[tid + 100]) * sinv[0];
            if (s + 1 < Sn) {
                if (((s + 1) & 3) == 0) {
                    if (tid == 0)
                        wait_flag_acquire(&g_flag[((s + 1) >> 2)*64 + b]);
                    barM();
                }
                const size_t tn = (size_t)(b*Sn + s + 1) * (Tn*Fp);
                stage_tile(sm_bytes + OFF_XW*4u, g_xw + tn, tid);
                stage_tile(sm_bytes + OFF_X*4u,  x    + tn, tid);
                cp_commit();
            }
            barM();

            // gx = satt @ Wx + bg (double-buffered L2 loads)
            if (tid < 300) {
                float wx1[25];
                #pragma unroll
                for (int q = 0; q < 25; q++)
                    wx1[q] = Wx[(25+q)*300 + tid];
                float acc = sbg[tid];
                #pragma unroll
                for (int q = 0; q < 25; q++)
                    acc = fmaf(satt[q], wx0[q], acc);
                #pragma unroll
                for (int q = 0; q < 25; q++)
                    wx0[q] = Wx[(50+q)*300 + tid];
                #pragma unroll
                for (int q = 0; q < 25; q++)
                    acc = fmaf(satt[25+q], wx1[q], acc);
                #pragma unroll
                for (int q = 0; q < 25; q++)
                    wx1[q] = Wx[(75+q)*300 + tid];
                #pragma unroll
                for (int q = 0; q < 25; q++)
                    acc = fmaf(satt[50+q], wx0[q], acc);
                #pragma unroll
                for (int q = 0; q < 25; q++)
                    acc = fmaf(satt[75+q], wx1[q], acc);
                sgx[tid] = acc;
            }
        }

        __syncthreads();   // join M (gx) and G (gh)

        // phase 5: GRU update + output
        if (tid < Fp) {
            float z  = fast_sigmoid(sgx[tid]       + sgh[tid]);
            float r  = fast_sigmoid(sgx[tid + 100] + sgh[tid + 100]);
            float ht = tanh_fast(sgx[tid + 200] + r * sgh[tid + 200]);
            float hn = (1.f - z) * sh[tid] + z * ht;
            out[((size_t)(b*Sn + s))*Fp + tid] = hn;
            sh[tid] = hn;
        }
        __syncthreads();   // publish sh for next step
    }
}

// ---------------------------------------------------------------------------
// Fused kernel: blockIdx < 64 -> scan CTA; else persistent GEMM worker.
// grid = 148 CTAs, 1 CTA/SM (219.5KB smem) -> all co-resident, no deadlock.
// ---------------------------------------------------------------------------
__global__ void __launch_bounds__(NT, 1) fused_kernel(
    const float* __restrict__ x,
    const float* __restrict__ W,
    const float* __restrict__ Wc,
    const float* __restrict__ bias,
    const float* __restrict__ u,
    const float* __restrict__ Wx,
    const float* __restrict__ Wh,
    const float* __restrict__ bg,
    float* __restrict__ out)
{
    extern __shared__ float sm[];
    if (blockIdx.x >= NSCAN) {
        gemm_body(x, W, bias, sm);
    } else {
        scan_body(x, Wc, u, Wx, Wh, bg, out, sm);
    }
}

// ---------------------------------------------------------------------------
extern "C" void kernel_launch(void* const* d_in, const int* in_sizes, int n_in,
                              void* d_out, int out_size)
{
    const float* x    = (const float*)d_in[0];
    const float* W    = (const float*)d_in[1];
    const float* Wc   = (const float*)d_in[2];
    const float* bias = (const float*)d_in[3];
    const float* u    = (const float*)d_in[4];
    const float* Wx   = (const float*)d_in[5];
    const float* Wh   = (const float*)d_in[6];
    const float* bg   = (const float*)d_in[7];
    float* out = (float*)d_out;

    cudaFuncSetAttribute(fused_kernel,
        cudaFuncAttributeMaxDynamicSharedMemorySize, SCAN_SMEM_BYTES);

    zero_flags_kernel<<<2, 1024>>>();
    fused_kernel<<<NSCAN + NWORK, NT, SCAN_SMEM_BYTES>>>(
        x, W, Wc, bias, u, Wx, Wh, bg, out);
}

// round 13
// speedup vs baseline: 1.0607x; 1.0607x over previous
#include <cuda_runtime.h>
#include <cuda_bf16.h>
#include <cstdint>

// Problem constants
#define Bn 64
#define Sn 128
#define Tn 64
#define Fp 100
#define M_TOTAL (Bn*Sn*Tn)   // 524288

#define NSCAN   64           // scan CTAs (one per batch)
#define NWORK   84           // GEMM worker CTAs
#define NBLK    2048         // 256-row GEMM blocks total (64 b x 32 groups)

__device__ float g_xw[(size_t)M_TOTAL * Fp];
__device__ int   g_flag[NBLK];

namespace {
struct ForceLoad {
    ForceLoad() {
        void* p = nullptr;
        cudaGetSymbolAddress(&p, g_xw);
        cudaGetSymbolAddress(&p, g_flag);
    }
};
ForceLoad g_force_load_;
}

// ---------------------------------------------------------------------------
// Shared constants / helpers
// ---------------------------------------------------------------------------
#define GMT 256
#define SX_LD 258
#define SW_LD 104

#define NT 512
#define NM 384
#define TILE_LD 104
#define TILE_CHUNKS (Tn*(Fp/4))    // 1600 x 16B

// scan SMEM float offsets (GEMM workers reuse the front of the same buffer)
#define OFF_WH    0       // 30000
#define OFF_WC    30000   // 10000
#define OFF_XW    40000   // 6656
#define OFF_X     46656   // 6656
#define OFF_U     53312   // 100
#define OFF_BG    53412   // 300
#define OFF_H     53712   // 100
#define OFF_C     53812   // 100
#define OFF_A     53912   // 64
#define OFF_PART  53976   // 200
#define OFF_GX    54176   // 300
#define OFF_GH    54476   // 300
#define OFF_ATT   54776   // 100
#define OFF_INV   54876   // 4
#define SCAN_SMEM_FLOATS 54880
#define SCAN_SMEM_BYTES (SCAN_SMEM_FLOATS*4)   // 219520

__device__ __forceinline__ unsigned long long pack2(float a, float b) {
    unsigned long long r;
    asm("mov.b64 %0, {%1, %2};" : "=l"(r) : "f"(a), "f"(b));
    return r;
}
__device__ __forceinline__ float2 unpack2(unsigned long long v) {
    float2 r;
    asm("mov.b64 {%0, %1}, %2;" : "=f"(r.x), "=f"(r.y) : "l"(v));
    return r;
}
__device__ __forceinline__ float tanh_fast(float x) {
    float y;
    asm("tanh.approx.f32 %0, %1;" : "=f"(y) : "f"(x));
    return y;
}
__device__ __forceinline__ float fast_sigmoid(float v) {
    return 1.f / (1.f + __expf(-v));
}
__device__ __forceinline__ void cp_async16(uint32_t smem_addr, const void* gptr) {
    asm volatile("cp.async.cg.shared.global [%0], [%1], 16;"
                 :: "r"(smem_addr), "l"(gptr));
}
__device__ __forceinline__ void cp_commit() {
    asm volatile("cp.async.commit_group;");
}
__device__ __forceinline__ void cp_wait0() {
    asm volatile("cp.async.wait_group 0;");
}
__device__ __forceinline__ void barM() {
    asm volatile("bar.sync 1, %0;" :: "n"(NM) : "memory");
}
__device__ __forceinline__ void set_flag_release(int* p) {
    asm volatile("st.release.gpu.global.b32 [%0], %1;" :: "l"(p), "r"(1) : "memory");
}
__device__ __forceinline__ void wait_flag_acquire(const int* p) {
    int v;
    while (true) {
        asm volatile("ld.acquire.gpu.global.b32 %0, [%1];" : "=r"(v) : "l"(p) : "memory");
        if (v) break;
        __nanosleep(64);
    }
}

// ---------------------------------------------------------------------------
// flag reset (must precede fused kernel every call; deterministic per replay)
// ---------------------------------------------------------------------------
__global__ void zero_flags_kernel() {
    int i = blockIdx.x * blockDim.x + threadIdx.x;
    if (i < NBLK) g_flag[i] = 0;
}

// ---------------------------------------------------------------------------
// GEMM worker body: persistent loop over blocks j = w, w+NWORK, ...
// j -> (b = j & 63, g = j >> 6); block rows m0 = b*8192 + g*256.
// g-major global order => for step s, scan CTA b needs flag[(s>>2)*64 + b].
// Threads 0..415 compute (32 m-lanes x 13 n-groups, 8x8 f32x2 tile);
// threads 416..511 only help with loads / barriers.
// ---------------------------------------------------------------------------
__device__ void gemm_body(const float* __restrict__ x,
                          const float* __restrict__ W,
                          const float* __restrict__ bias,
                          float* sm)
{
    float* sX = sm;                  // [100][SX_LD]
    float* sW = sm + Fp*SX_LD;       // [100][SW_LD]

    const int tid = threadIdx.x;
    const int w   = blockIdx.x - NSCAN;

    // W (+pad) loaded once, reused across all blocks of this worker
    for (int i = tid; i < Fp*SW_LD; i += NT) {
        int k = i / SW_LD, n = i - k*SW_LD;
        sW[i] = (n < Fp) ? W[k*Fp + n] : 0.f;
    }

    const bool active = (tid < 416);
    const int mi = tid & 31;
    const int ni = tid >> 5;
    const int nbase = ni * 8;
    const uint32_t sa = (uint32_t)__cvta_generic_to_shared(sX) + (uint32_t)mi*8u;
    const float* wrow = sW + nbase;

    float bb[8];
    if (active) {
        #pragma unroll
        for (int n = 0; n < 8; n++) {
            int nb = nbase + n;
            bb[n] = (nb < Fp) ? bias[nb] : 0.f;
        }
    }

    for (int j = w; j < NBLK; j += NWORK) {
        const int b = j & 63;
        const int g = j >> 6;
        const size_t m0 = (size_t)b * (Sn*(size_t)Tn) + (size_t)g * GMT;

        __syncthreads();   // prior block's sX reads done (also publishes sW 1st iter)
        for (int i = tid; i < GMT*Fp; i += NT) {
            int m = i / Fp, k = i - m*Fp;
            sX[k*SX_LD + m] = x[(m0 + m)*Fp + k];
        }
        __syncthreads();

        if (active) {
            unsigned long long acc[4][8];
            #pragma unroll
            for (int p = 0; p < 4; p++)
                #pragma unroll
                for (int n = 0; n < 8; n++) acc[p][n] = 0ull;

            #pragma unroll 2
            for (int k = 0; k < Fp; k++) {
                unsigned long long ap[4];
                #pragma unroll
                for (int p = 0; p < 4; p++)
                    asm("ld.shared.b64 %0, [%1];"
                        : "=l"(ap[p])
                        : "r"(sa + (uint32_t)((k*SX_LD + 64*p)*4)));
                float4 b0 = *(const float4*)(wrow + k*SW_LD);
                float4 b1 = *(const float4*)(wrow + k*SW_LD + 4);
                unsigned long long bd[8];
                bd[0] = pack2(b0.x, b0.x); bd[1] = pack2(b0.y, b0.y);
                bd[2] = pack2(b0.z, b0.z); bd[3] = pack2(b0.w, b0.w);
                bd[4] = pack2(b1.x, b1.x); bd[5] = pack2(b1.y, b1.y);
                bd[6] = pack2(b1.z, b1.z); bd[7] = pack2(b1.w, b1.w);
                #pragma unroll
                for (int p = 0; p < 4; p++)
                    #pragma unroll
                    for (int n = 0; n < 8; n++)
                        asm("fma.rn.f32x2 %0, %1, %2, %0;"
                            : "+l"(acc[p][n]) : "l"(ap[p]), "l"(bd[n]));
            }

            #pragma unroll
            for (int p = 0; p < 4; p++) {
                float2 v[8];
                #pragma unroll
                for (int n = 0; n < 8; n++) v[n] = unpack2(acc[p][n]);
                const size_t r0 = m0 + 2*mi + 64*p;
                float* o0 = g_xw + r0*Fp + nbase;
                float* o1 = o0 + Fp;
                float4 lo0 = { v[0].x+bb[0], v[1].x+bb[1], v[2].x+bb[2], v[3].x+bb[3] };
                float4 lo1 = { v[0].y+bb[0], v[1].y+bb[1], v[2].y+bb[2], v[3].y+bb[3] };
                *(float4*)o0 = lo0;
                *(float4*)o1 = lo1;
                if (ni < 12) {
                    float4 hi0 = { v[4].x+bb[4], v[5].x+bb[5], v[6].x+bb[6], v[7].x+bb[7] };
                    float4 hi1 = { v[4].y+bb[4], v[5].y+bb[5], v[6].y+bb[6], v[7].y+bb[7] };
                    *(float4*)(o0 + 4) = hi0;
                    *(float4*)(o1 + 4) = hi1;
                }
            }
        }

        __threadfence();     // each thread's g_xw stores visible at gpu scope
        __syncthreads();     // ...for ALL threads, before the flag
        if (tid == 0) set_flag_release(&g_flag[j]);
    }
}

// ---------------------------------------------------------------------------
// scan tile staging
// ---------------------------------------------------------------------------
__device__ __forceinline__ void stage_tile(uint32_t smem_base_bytes,
                                           const float* gsrc, int tid) {
    #pragma unroll 2
    for (int i = tid; i < TILE_CHUNKS; i += NM) {
        int t = i / (Fp/4);
        int c = i - t*(Fp/4);
        cp_async16(smem_base_bytes + (uint32_t)(t*TILE_LD + c*4)*4u,
                   gsrc + (size_t)i*4);
    }
}

// ---------------------------------------------------------------------------
// Scan body: identical to R8 warp-specialized scan + producer flag waits.
// ---------------------------------------------------------------------------
__device__ void scan_body(const float* __restrict__ x,
                          const float* __restrict__ Wc,
                          const float* __restrict__ u,
                          const float* __restrict__ Wx,
                          const float* __restrict__ Wh,
                          const float* __restrict__ bg,
                          float* __restrict__ out,
                          float* sm)
{
    float* sWh  = sm + OFF_WH;
    float* sWc  = sm + OFF_WC;
    float* sXW  = sm + OFF_XW;
    float* sX   = sm + OFF_X;
    float* su   = sm + OFF_U;
    float* sbg  = sm + OFF_BG;
    float* sh   = sm + OFF_H;
    float* sc   = sm + OFF_C;
    float* sa   = sm + OFF_A;
    float* spart= sm + OFF_PART;
    float* sgx  = sm + OFF_GX;
    float* sgh  = sm + OFF_GH;
    float* satt = sm + OFF_ATT;
    float* sinv = sm + OFF_INV;

    const int tid  = threadIdx.x;
    const int lane = tid & 31;
    const int wid  = tid >> 5;   // 0..15
    const int b    = blockIdx.x;
    const bool isM = (tid < NM);

    const uint32_t sm_bytes = (uint32_t)__cvta_generic_to_shared(sm);

    // weights first (overlaps the GEMM producing group 0)
    {
        const float4* wh4 = (const float4*)Wh;
        float4* swh4 = (float4*)sWh;
        for (int i = tid; i < (Fp*3*Fp)/4; i += NT) swh4[i] = wh4[i];
        const float4* wc4 = (const float4*)Wc;
        float4* swc4 = (float4*)sWc;
        for (int i = tid; i < (Fp*Fp)/4; i += NT) swc4[i] = wc4[i];
    }
    if (tid < Fp)   { su[tid] = u[tid]; sh[tid] = 0.f; }
    if (tid < 3*Fp) sbg[tid] = bg[tid];

    if (isM) {
        if (tid == 0) wait_flag_acquire(&g_flag[b]);   // block (b, g=0)
        barM();
        const size_t tile0 = (size_t)(b*Sn) * (Tn*Fp);
        stage_tile(sm_bytes + OFF_XW*4u, g_xw + tile0, tid);
        stage_tile(sm_bytes + OFF_X*4u,  x    + tile0, tid);
        cp_commit();
    }
    __syncthreads();

    const float u0 = su[lane];
    const float u1 = su[lane + 32];
    const float u2 = su[lane + 64];
    const float u3 = (lane < 4) ? su[lane + 96] : 0.f;

    for (int s = 0; s < Sn; s++) {
        if (!isM) {
            // ===== group G: gh = h @ Wh =====
            const int tg = tid - NM;   // 0..127
            float g0 = 0.f, g1 = 0.f, g2 = 0.f;
            #pragma unroll 4
            for (int i = 0; i < Fp; i++) {
                const float hv = sh[i];
                const float* wr = sWh + i*300 + tg;
                g0 = fmaf(hv, wr[0],   g0);
                g1 = fmaf(hv, wr[128], g1);
                g2 = fmaf(hv, wr[256], g2);
            }
            sgh[tg]       = g0;
            sgh[tg + 128] = g1;
            if (tg < 44) sgh[tg + 256] = g2;
        } else {
            // ===== group M =====
            float wx0[25];
            if (tid < 300) {
                #pragma unroll
                for (int q = 0; q < 25; q++)
                    wx0[q] = Wx[q*300 + tid];
            }

            // phase 1: c = h @ W_context
            if (tid < Fp) {
                float a0=0.f, a1=0.f, a2=0.f, a3=0.f;
                #pragma unroll 5
                for (int i = 0; i < Fp; i += 4) {
                    a0 += sh[i+0] * sWc[(i+0)*Fp + tid];
                    a1 += sh[i+1] * sWc[(i+1)*Fp + tid];
                    a2 += sh[i+2] * sWc[(i+2)*Fp + tid];
                    a3 += sh[i+3] * sWc[(i+3)*Fp + tid];
                }
                sc[tid] = (a0 + a1) + (a2 + a3);
            }
            cp_wait0();
            barM();

            // phase 2: a[t] = exp( tanh(xw[t,:] + c) . u )
            {
                const float c0 = sc[lane];
                const float c1 = sc[lane + 32];
                const float c2 = sc[lane + 64];
                const float c3 = (lane < 4) ? sc[lane + 96] : 0.f;
                #pragma unroll
                for (int t = wid; t < Tn; t += 12) {
                    const float* row = sXW + t*TILE_LD;
                    float v0 = row[lane]      + c0;
                    float v1 = row[lane + 32] + c1;
                    float v2 = row[lane + 64] + c2;
                    float v3 = (lane < 4) ? (row[lane + 96] + c3) : 0.f;
                    float p = tanh_fast(v0)*u0 + tanh_fast(v1)*u1
                            + tanh_fast(v2)*u2 + tanh_fast(v3)*u3;
                    #pragma unroll
                    for (int off = 16; off > 0; off >>= 1)
                        p += __shfl_xor_sync(0xffffffffu, p, off);
                    if (lane == 0) sa[t] = __expf(p);
                }
            }
            barM();

            // phase 2b (warp 11) + phase 3 partials (tid<200)
            if (wid == 11) {
                float v = sa[lane] + sa[lane + 32];
                #pragma unroll
                for (int off = 16; off > 0; off >>= 1)
                    v += __shfl_xor_sync(0xffffffffu, v, off);
                if (lane == 0) sinv[0] = 1.f / (v + 1e-7f);
            }
            if (tid < 200) {
                const int f    = (tid < 100) ? tid : tid - 100;
                const int half = (tid < 100) ? 0 : 1;
                const float* xr = sX + (half*32)*TILE_LD + f;
                const float* ar = sa + half*32;
                float acc = 0.f;
                #pragma unroll 8
                for (int t = 0; t < 32; t++)
                    acc += xr[t*TILE_LD] * ar[t];
                spart[tid] = acc;
            }
            barM();

            // phase 3b: attended; prefetch next step's tiles (flag-gated)
            if (tid < Fp) satt[tid] = (spart[tid] + spart[tid + 100]) * sinv[0];
            if (s + 1 < Sn) {
                if (((s + 1) & 3) == 0) {
                    if (tid == 0)
                        wait_flag_acquire(&g_flag[((s + 1) >> 2)*64 + b]);
                    barM();
                }
                const size_t tn = (size_t)(b*Sn + s + 1) * (Tn*Fp);
                stage_tile(sm_bytes + OFF_XW*4u, g_xw + tn, tid);
                stage_tile(sm_bytes + OFF_X*4u,  x    + tn, tid);
                cp_commit();
            }
            barM();

            // gx = satt @ Wx + bg (double-buffered L2 loads)
            if (tid < 300) {
                float wx1[25];
                #pragma unroll
                for (int q = 0; q < 25; q++)
                    wx1[q] = Wx[(25+q)*300 + tid];
                float acc = sbg[tid];
                #pragma unroll
                for (int q = 0; q < 25; q++)
                    acc = fmaf(satt[q], wx0[q], acc);
                #pragma unroll
                for (int q = 0; q < 25; q++)
                    wx0[q] = Wx[(50+q)*300 + tid];
                #pragma unroll
                for (int q = 0; q < 25; q++)
                    acc = fmaf(satt[25+q], wx1[q], acc);
                #pragma unroll
                for (int q = 0; q < 25; q++)
                    wx1[q] = Wx[(75+q)*300 + tid];
                #pragma unroll
                for (int q = 0; q < 25; q++)
                    acc = fmaf(satt[50+q], wx0[q], acc);
                #pragma unroll
                for (int q = 0; q < 25; q++)
                    acc = fmaf(satt[75+q], wx1[q], acc);
                sgx[tid] = acc;
            }
        }

        __syncthreads();   // join M (gx) and G (gh)

        // phase 5: GRU update + output
        if (tid < Fp) {
            float z  = fast_sigmoid(sgx[tid]       + sgh[tid]);
            float r  = fast_sigmoid(sgx[tid + 100] + sgh[tid + 100]);
            float ht = tanh_fast(sgx[tid + 200] + r * sgh[tid + 200]);
            float hn = (1.f - z) * sh[tid] + z * ht;
            out[((size_t)(b*Sn + s))*Fp + tid] = hn;
            sh[tid] = hn;
        }
        __syncthreads();   // publish sh for next step
    }
}

// ---------------------------------------------------------------------------
// Fused kernel: blockIdx < 64 -> scan CTA; else persistent GEMM worker.
// grid = 148 CTAs, 1 CTA/SM (219.5KB smem) -> all co-resident, no deadlock.
// ---------------------------------------------------------------------------
__global__ void __launch_bounds__(NT, 1) fused_kernel(
    const float* __restrict__ x,
    const float* __restrict__ W,
    const float* __restrict__ Wc,
    const float* __restrict__ bias,
    const float* __restrict__ u,
    const float* __restrict__ Wx,
    const float* __restrict__ Wh,
    const float* __restrict__ bg,
    float* __restrict__ out)
{
    extern __shared__ float sm[];
    if (blockIdx.x >= NSCAN) {
        gemm_body(x, W, bias, sm);
    } else {
        scan_body(x, Wc, u, Wx, Wh, bg, out, sm);
    }
}

// ---------------------------------------------------------------------------
extern "C" void kernel_launch(void* const* d_in, const int* in_sizes, int n_in,
                              void* d_out, int out_size)
{
    const float* x    = (const float*)d_in[0];
    const float* W    = (const float*)d_in[1];
    const float* Wc   = (const float*)d_in[2];
    const float* bias = (const float*)d_in[3];
    const float* u    = (const float*)d_in[4];
    const float* Wx   = (const float*)d_in[5];
    const float* Wh   = (const float*)d_in[6];
    const float* bg   = (const float*)d_in[7];
    float* out = (float*)d_out;

    cudaFuncSetAttribute(fused_kernel,
        cudaFuncAttributeMaxDynamicSharedMemorySize, SCAN_SMEM_BYTES);

    zero_flags_kernel<<<2, 1024>>>();
    fused_kernel<<<NSCAN + NWORK, NT, SCAN_SMEM_BYTES>>>(
        x, W, Wc, bias, u, Wx, Wh, bg, out);
}